// round 8
// baseline (speedup 1.0000x reference)
#include <cuda_runtime.h>
#include <cstdint>

// Problem constants (fixed by the dataset)
#define BATCH      16
#define NPTS       131072
#define KCENT      1024
#define NBLK       8                    // blocks cooperating per batch
#define CHUNK      (NPTS / NBLK)        // 16384 points per block
#define THREADS    512
#define PT_PER_T   (CHUNK / THREADS)    // 32 dist values in registers per thread
#define GROUPS     (PT_PER_T / 4)       // 8 float4 groups per thread

// Cross-block communication (device globals: no allocation allowed)
__device__ unsigned long long g_best[BATCH][2][NBLK];  // per-iter partials (double-buffered)
__device__ unsigned           g_cnt[BATCH];            // monotonic barrier counters

// Diagnostic: pre-fill output with 65536.0f. If the main kernel never runs,
// rel_err lands near 0.5 (vs 1.0 for all-zero) => launch bug, not data bug.
__global__ void fps_fill_kernel(float* out) {
    int i = blockIdx.x * blockDim.x + threadIdx.x;
    if (i < BATCH * KCENT) out[i] = 65536.0f;
}

__global__ void fps_init_kernel() {
    const int t = threadIdx.x;
    if (t < BATCH) g_cnt[t] = 0u;
    if (t < BATCH * 2 * NBLK)
        ((unsigned long long*)g_best)[t] = 0ull;
}

// Coordinates are read from global memory every iteration. Each block touches
// only its own 196 KB chunk => L1D-resident (228 KB L1, not flushed within a
// launch) => iterations 2..1024 run at L1 bandwidth. No smem opt-in needed.
__global__ void __launch_bounds__(THREADS, 1)
fps_kernel(const float* __restrict__ pt, float* __restrict__ out) {
    const int blk = blockIdx.x;        // 0..127
    const int b   = blk / NBLK;        // batch
    const int sub = blk % NBLK;        // sub-block within batch
    const int tid = threadIdx.x;

    __shared__ unsigned long long s_red[THREADS / 32];
    __shared__ float s_p[3];
    __shared__ int   s_cur;

    const float* px_g = pt + (size_t)b * 3 * NPTS;
    const float* py_g = px_g + NPTS;
    const float* pz_g = px_g + 2 * NPTS;
    const int base = sub * CHUNK;

    const float4* __restrict__ gx = reinterpret_cast<const float4*>(px_g + base);
    const float4* __restrict__ gy = reinterpret_cast<const float4*>(py_g + base);
    const float4* __restrict__ gz = reinterpret_cast<const float4*>(pz_g + base);

    // ---- register-resident min-distance array
    float dist[PT_PER_T];
#pragma unroll
    for (int i = 0; i < PT_PER_T; i++) dist[i] = __int_as_float(0x7f800000);  // +inf

    if (tid == 0) {
        s_cur  = 0;
        s_p[0] = px_g[0];
        s_p[1] = py_g[0];
        s_p[2] = pz_g[0];
    }
    __syncthreads();

    for (int k = 0; k < KCENT; k++) {
        const int   cur = s_cur;
        const float cx = s_p[0], cy = s_p[1], cz = s_p[2];

        // OUTPUT IS float32 (metadata __output__): indices < 2^24 are exact.
        if (sub == 0 && tid == 0) out[b * KCENT + k] = (float)cur;

        // ---- update dists & local argmax (indices ascend, so strict '>' keeps first max)
        float best_d = -1.0f;
        int   best_i = 0;
#pragma unroll
        for (int g = 0; g < GROUPS; g++) {
            const int vi = g * THREADS + tid;
            const float4 x4 = gx[vi];
            const float4 y4 = gy[vi];
            const float4 z4 = gz[vi];
            const int p0 = base + vi * 4;
            const float xs[4] = {x4.x, x4.y, x4.z, x4.w};
            const float ys[4] = {y4.x, y4.y, y4.z, y4.w};
            const float zs[4] = {z4.x, z4.y, z4.z, z4.w};
#pragma unroll
            for (int j = 0; j < 4; j++) {
                // no-FMA-contraction arithmetic: ((dx*dx)+(dy*dy))+(dz*dz)
                const float dx = __fadd_rn(xs[j], -cx);
                const float dy = __fadd_rn(ys[j], -cy);
                const float dz = __fadd_rn(zs[j], -cz);
                const float d  = __fadd_rn(__fadd_rn(__fmul_rn(dx, dx),
                                                     __fmul_rn(dy, dy)),
                                           __fmul_rn(dz, dz));
                const float nd = fminf(dist[g * 4 + j], d);
                dist[g * 4 + j] = nd;
                if (nd > best_d) { best_d = nd; best_i = p0 + j; }
            }
        }

        // ---- pack (dist, ~idx): max over packed == max dist, ties -> lowest idx.
        // Valid because all dists are >= 0 finite (or +inf) -> bit pattern monotonic.
        unsigned long long key =
            ((unsigned long long)__float_as_uint(best_d) << 32) |
            (unsigned)(~(unsigned)best_i);

        // warp reduce
#pragma unroll
        for (int off = 16; off > 0; off >>= 1) {
            unsigned long long o = __shfl_down_sync(0xffffffffu, key, off);
            if (o > key) key = o;
        }
        if ((tid & 31) == 0) s_red[tid >> 5] = key;
        __syncthreads();

        if (tid == 0) {
            unsigned long long bb = s_red[0];
#pragma unroll
            for (int w = 1; w < THREADS / 32; w++)
                if (s_red[w] > bb) bb = s_red[w];

            // publish partial, fence, arrive, BOUNDED spin on per-batch barrier.
            // All 128 blocks are co-resident (1 wave on 148 SMs) => bound never
            // trips in practice; it exists to avoid hanging if that breaks.
            *(volatile unsigned long long*)&g_best[b][k & 1][sub] = bb;
            __threadfence();
            atomicAdd(&g_cnt[b], 1u);
            const unsigned target = (unsigned)(NBLK * (k + 1));
            unsigned spin = 0;
            while (*(volatile unsigned*)&g_cnt[b] < target) {
                if (++spin > (1u << 22)) break;   // ~hundreds of ms worst case
                __nanosleep(32);
            }
            __threadfence();

            // reduce the 8 per-block partials (every block does this identically)
            unsigned long long gb = *(volatile unsigned long long*)&g_best[b][k & 1][0];
#pragma unroll
            for (int j = 1; j < NBLK; j++) {
                unsigned long long v = *(volatile unsigned long long*)&g_best[b][k & 1][j];
                if (v > gb) gb = v;
            }
            const int nxt = (int)(~(unsigned)(gb & 0xffffffffu));
            s_cur  = nxt;
            s_p[0] = px_g[nxt];
            s_p[1] = py_g[nxt];
            s_p[2] = pz_g[nxt];
        }
        __syncthreads();
    }
}

extern "C" void kernel_launch(void* const* d_in, const int* in_sizes, int n_in,
                              void* d_out, int out_size) {
    // Select the coordinate buffer by SIZE, not position (robust to metadata
    // ordering and element/byte units): pt has 16*3*131072 = 6291456 elements.
    const float* ptc = nullptr;
    for (int i = 0; i < n_in; i++) {
        if (in_sizes[i] == BATCH * 3 * NPTS) { ptc = (const float*)d_in[i]; break; }
    }
    if (!ptc) {  // fallback: largest input
        int bi = 0;
        for (int i = 1; i < n_in; i++) if (in_sizes[i] > in_sizes[bi]) bi = i;
        ptc = (const float*)d_in[bi];
    }
    float* out = (float*)d_out;
    (void)out_size;

    fps_fill_kernel<<<(BATCH * KCENT + 255) / 256, 256>>>(out);
    fps_init_kernel<<<1, 256>>>();
    fps_kernel<<<BATCH * NBLK, THREADS>>>(ptc, out);
}